// round 8
// baseline (speedup 1.0000x reference)
#include <cuda_runtime.h>
#include <cuda_bf16.h>
#include <cstdint>
#include <math.h>

#define BSZ 8
#define CDIM 768
#define LDIM 4096
#define NH 12
#define HD 64
#define CHK 64
#define NCHK (LDIM/CHK)
#define MTOT (BSZ*LDIM)
#define SP 65

// ---------------- scratch (device globals; no allocation allowed) ----------------
__device__ unsigned short g_xh[(size_t)MTOT * CDIM];   // bf16 hi of x^T [m][k]
__device__ unsigned short g_xl[(size_t)MTOT * CDIM];   // bf16 lo
__device__ unsigned short g_wh[(size_t)4 * CDIM * CDIM]; // W^T [w*768+n][k], w: 0 q,1 k,2 v,3 o
__device__ unsigned short g_wl[(size_t)4 * CDIM * CDIM];
__device__ float g_q[(size_t)BSZ * NH * LDIM * HD];
__device__ float g_k[(size_t)BSZ * NH * LDIM * HD];
__device__ float g_v[(size_t)BSZ * NH * LDIM * HD];
__device__ float g_beta[(size_t)BSZ * NH * LDIM];
__device__ unsigned short g_oh[(size_t)MTOT * CDIM];   // bf16 hi of o [m][c]
__device__ unsigned short g_ol[(size_t)MTOT * CDIM];   // bf16 lo

// ---------------- PTX helpers (base-PTX only; no 'a' features) ----------------
__device__ __forceinline__ uint32_t smem_u32(const void* p) {
    return (uint32_t)__cvta_generic_to_shared(p);
}
__device__ __forceinline__ void cp16(uint32_t dst, const void* src) {
    asm volatile("cp.async.cg.shared.global [%0], [%1], 16;" :: "r"(dst), "l"(src) : "memory");
}
__device__ __forceinline__ void cp_commit() {
    asm volatile("cp.async.commit_group;" ::: "memory");
}
__device__ __forceinline__ void cp_wait1() {
    asm volatile("cp.async.wait_group 1;" ::: "memory");
}
__device__ __forceinline__ void cp_wait0() {
    asm volatile("cp.async.wait_group 0;" ::: "memory");
}
__device__ __forceinline__ void ldsm_x4(uint32_t addr, uint32_t* r) {
    asm volatile("ldmatrix.sync.aligned.m8n8.x4.shared.b16 {%0,%1,%2,%3}, [%4];"
                 : "=r"(r[0]), "=r"(r[1]), "=r"(r[2]), "=r"(r[3]) : "r"(addr));
}
__device__ __forceinline__ void mma_bf16(float* d, const uint32_t* a, const uint32_t* b) {
    asm volatile("mma.sync.aligned.m16n8k16.row.col.f32.bf16.bf16.f32 "
                 "{%0,%1,%2,%3}, {%4,%5,%6,%7}, {%8,%9}, {%0,%1,%2,%3};"
                 : "+f"(d[0]), "+f"(d[1]), "+f"(d[2]), "+f"(d[3])
                 : "r"(a[0]), "r"(a[1]), "r"(a[2]), "r"(a[3]), "r"(b[0]), "r"(b[1]));
}
__device__ __forceinline__ void hilo(float v, unsigned short& h, unsigned short& l) {
    uint32_t u = __float_as_uint(v);
    h = (unsigned short)(u >> 16);
    float lf = v - __uint_as_float(u & 0xFFFF0000u);
    __nv_bfloat16 lb = __float2bfloat16(lf);
    l = *reinterpret_cast<unsigned short*>(&lb);
}

// ---------------- prep: transpose + hi/lo split ----------------
__global__ void __launch_bounds__(256) prep_x(const float* __restrict__ x) {
    __shared__ float t[32][33];
    const int tid = threadIdx.x;
    const int b = blockIdx.z, c0 = blockIdx.y * 32, l0 = blockIdx.x * 32;
    const int lt = tid & 31, ct = tid >> 5;
    const float* xb = x + ((size_t)b * CDIM + c0) * LDIM + l0;
#pragma unroll
    for (int i = 0; i < 4; i++) t[ct + 8 * i][lt] = xb[(size_t)(ct + 8 * i) * LDIM + lt];
    __syncthreads();
#pragma unroll
    for (int i = 0; i < 4; i++) {
        unsigned short h, l;
        hilo(t[lt][ct + 8 * i], h, l);
        size_t off = (size_t)(b * LDIM + l0 + ct + 8 * i) * CDIM + c0 + lt;
        g_xh[off] = h;
        g_xl[off] = l;
    }
}

__global__ void __launch_bounds__(256) prep_w(const float* __restrict__ Wq, const float* __restrict__ Wk,
                                              const float* __restrict__ Wv, const float* __restrict__ Wo) {
    __shared__ float t[32][33];
    const int tid = threadIdx.x;
    const int w = blockIdx.z, n0 = blockIdx.y * 32, k0 = blockIdx.x * 32;
    const int nt = tid & 31, kt = tid >> 5;
    const float* W = (w == 0) ? Wq : (w == 1) ? Wk : (w == 2) ? Wv : Wo;
#pragma unroll
    for (int i = 0; i < 4; i++) t[kt + 8 * i][nt] = W[(size_t)(k0 + kt + 8 * i) * CDIM + n0 + nt];
    __syncthreads();
#pragma unroll
    for (int i = 0; i < 4; i++) {
        unsigned short h, l;
        hilo(t[nt][kt + 8 * i], h, l);
        size_t off = (size_t)(w * CDIM + n0 + kt + 8 * i) * CDIM + k0 + nt;
        g_wh[off] = h;
        g_wl[off] = l;
    }
}

// ---------------- GEMM core: 128x128 block, 8 warps, K-chunk 64, hi/lo 3-pass ----------------
// stage: Ah[128][64] @0, Al @16384, Bh @32768, Bl @49152 (bf16, 128B rows, SW128 swizzle)
#define STG 65536
#define GEMM_SMEM (2 * STG)

__device__ __forceinline__ void load_stage(uint32_t st,
                                           const unsigned short* Ah, const unsigned short* Al,
                                           const unsigned short* Bh, const unsigned short* Bl,
                                           int ch, int tid) {
#pragma unroll
    for (int i = 0; i < 16; i++) {
        const int tile = i >> 2;
        const unsigned short* src0 = (tile == 0) ? Ah : (tile == 1) ? Al : (tile == 2) ? Bh : Bl;
        int rem = (i & 3) * 256 + tid;
        int row = rem >> 3, j = rem & 7;
        uint32_t off = row * 128 + j * 16;
        uint32_t sw = off ^ ((off >> 3) & 0x70);
        cp16(st + tile * 16384 + sw, src0 + (size_t)row * CDIM + ch * 64 + j * 8);
    }
}

__device__ __forceinline__ void gemm_compute(uint32_t st, float (&C)[2][8][4], int wid, int lane) {
    const int wm = wid >> 1, wn = wid & 1;
    const int rowA0 = wm * 32 + (lane & 15);
    const int byteA = (lane >> 4) * 16;
    const int rowB0 = wn * 64 + ((lane >> 4) & 1) * 8 + (lane & 7);
    const int byteB = ((lane >> 3) & 1) * 16;
#pragma unroll
    for (int ks = 0; ks < 4; ks++) {
        uint32_t ah[2][4], al[2][4], bh[4][4], bl[4][4];
#pragma unroll
        for (int ma = 0; ma < 2; ma++) {
            uint32_t off = (uint32_t)(rowA0 + ma * 16) * 128 + ks * 32 + byteA;
            uint32_t sw = off ^ ((off >> 3) & 0x70);
            ldsm_x4(st + sw, ah[ma]);
            ldsm_x4(st + 16384 + sw, al[ma]);
        }
#pragma unroll
        for (int jj = 0; jj < 4; jj++) {
            uint32_t off = (uint32_t)(rowB0 + jj * 16) * 128 + ks * 32 + byteB;
            uint32_t sw = off ^ ((off >> 3) & 0x70);
            ldsm_x4(st + 32768 + sw, bh[jj]);
            ldsm_x4(st + 49152 + sw, bl[jj]);
        }
#pragma unroll
        for (int ma = 0; ma < 2; ma++)
#pragma unroll
            for (int j = 0; j < 8; j++) {
                uint32_t* bhp = &bh[j >> 1][(j & 1) * 2];
                uint32_t* blp = &bl[j >> 1][(j & 1) * 2];
                mma_bf16(C[ma][j], ah[ma], bhp);
                mma_bf16(C[ma][j], al[ma], bhp);
                mma_bf16(C[ma][j], ah[ma], blp);
            }
    }
}

// ---------------- qkv GEMM: D = xt @ W^T, silu (+ l2norm for q,k) ----------------
__global__ void __launch_bounds__(256) qkv_gemm() {
    extern __shared__ char smg[];
    const uint32_t sb = smem_u32(smg);
    const int tid = threadIdx.x, wid = tid >> 5, lane = tid & 31;
    const int nt = blockIdx.x;
    const int m0 = blockIdx.y * 128;
    const unsigned short* Ah = g_xh + (size_t)m0 * CDIM;
    const unsigned short* Al = g_xl + (size_t)m0 * CDIM;
    const unsigned short* Bh = g_wh + (size_t)(nt * 128) * CDIM;
    const unsigned short* Bl = g_wl + (size_t)(nt * 128) * CDIM;

    float C[2][8][4];
#pragma unroll
    for (int a = 0; a < 2; a++)
#pragma unroll
        for (int b = 0; b < 8; b++)
#pragma unroll
            for (int c = 0; c < 4; c++) C[a][b][c] = 0.f;

    load_stage(sb, Ah, Al, Bh, Bl, 0, tid);
    cp_commit();
    for (int ch = 0; ch < 12; ch++) {
        if (ch < 11) {
            load_stage(sb + ((ch + 1) & 1) * STG, Ah, Al, Bh, Bl, ch + 1, tid);
            cp_commit();
            cp_wait1();
        } else {
            cp_wait0();
        }
        __syncthreads();
        gemm_compute(sb + (ch & 1) * STG, C, wid, lane);
        __syncthreads();
    }

    // epilogue
    const int wm = wid >> 1, wn = wid & 1;
    const int which = nt / 6;                 // 0 q, 1 k, 2 v
    const int head = (nt % 6) * 2 + wn;
    float* gout = (which == 0) ? g_q : (which == 1) ? g_k : g_v;
    const int g = lane >> 2, qd = lane & 3;
#pragma unroll
    for (int ma = 0; ma < 2; ma++) {
        float s[8][4];
        float ss0 = 0.f, ss1 = 0.f;
#pragma unroll
        for (int j = 0; j < 8; j++)
#pragma unroll
            for (int t = 0; t < 4; t++) {
                float v = C[ma][j][t];
                float sv = v / (1.f + __expf(-v));
                s[j][t] = sv;
                if (t < 2) ss0 = fmaf(sv, sv, ss0);
                else       ss1 = fmaf(sv, sv, ss1);
            }
        ss0 += __shfl_xor_sync(0xFFFFFFFFu, ss0, 1);
        ss0 += __shfl_xor_sync(0xFFFFFFFFu, ss0, 2);
        ss1 += __shfl_xor_sync(0xFFFFFFFFu, ss1, 1);
        ss1 += __shfl_xor_sync(0xFFFFFFFFu, ss1, 2);
        float sc0 = (which < 2) ? rsqrtf(ss0 + 1e-6f) : 1.f;
        float sc1 = (which < 2) ? rsqrtf(ss1 + 1e-6f) : 1.f;
#pragma unroll
        for (int half = 0; half < 2; half++) {
            int m = m0 + wm * 32 + ma * 16 + g + half * 8;
            int b = m >> 12, l = m & 4095;
            float sc = half ? sc1 : sc0;
            float* op = gout + ((size_t)(b * NH + head) * LDIM + l) * HD + qd * 2;
#pragma unroll
            for (int j = 0; j < 8; j++) {
                float2 o2 = {s[j][half * 2] * sc, s[j][half * 2 + 1] * sc};
                *(float2*)(op + j * 8) = o2;
            }
        }
    }
}

// ---------------- out GEMM: y = o @ Wo^T, out[b,c,l] = x + y^T ----------------
__global__ void __launch_bounds__(256) out_gemm(const float* __restrict__ x, float* __restrict__ out) {
    extern __shared__ char smg2[];
    const uint32_t sb = smem_u32(smg2);
    const int tid = threadIdx.x, wid = tid >> 5, lane = tid & 31;
    const int n0 = blockIdx.x * 128;
    const int m0 = blockIdx.y * 128;
    const unsigned short* Ah = g_oh + (size_t)m0 * CDIM;
    const unsigned short* Al = g_ol + (size_t)m0 * CDIM;
    const unsigned short* Bh = g_wh + (size_t)(3 * CDIM + n0) * CDIM;
    const unsigned short* Bl = g_wl + (size_t)(3 * CDIM + n0) * CDIM;

    float C[2][8][4];
#pragma unroll
    for (int a = 0; a < 2; a++)
#pragma unroll
        for (int b = 0; b < 8; b++)
#pragma unroll
            for (int c = 0; c < 4; c++) C[a][b][c] = 0.f;

    load_stage(sb, Ah, Al, Bh, Bl, 0, tid);
    cp_commit();
    for (int ch = 0; ch < 12; ch++) {
        if (ch < 11) {
            load_stage(sb + ((ch + 1) & 1) * STG, Ah, Al, Bh, Bl, ch + 1, tid);
            cp_commit();
            cp_wait1();
        } else {
            cp_wait0();
        }
        __syncthreads();
        gemm_compute(sb + (ch & 1) * STG, C, wid, lane);
        __syncthreads();
    }

    // epilogue: transpose through smem, residual add, coalesced [B,C,L] writes
    float* smT = (float*)smg2;   // [128 c][132]
    const int wm = wid >> 1, wn = wid & 1;
    const int g = lane >> 2, qd = lane & 3;
#pragma unroll
    for (int ma = 0; ma < 2; ma++)
#pragma unroll
        for (int j = 0; j < 8; j++) {
            int r = wm * 32 + ma * 16 + g;
            int c = wn * 64 + j * 8 + qd * 2;
            smT[c * 132 + r]           = C[ma][j][0];
            smT[(c + 1) * 132 + r]     = C[ma][j][1];
            smT[c * 132 + r + 8]       = C[ma][j][2];
            smT[(c + 1) * 132 + r + 8] = C[ma][j][3];
        }
    __syncthreads();

    const int b = m0 >> 12, l0 = m0 & 4095;
#pragma unroll
    for (int i = 0; i < 16; i++) {
        int u = tid + i * 256;
        int c = u >> 5, l4 = (u & 31) * 4;
        size_t gi = ((size_t)b * CDIM + n0 + c) * LDIM + l0 + l4;
        float4 xr = *(const float4*)(x + gi);
        float4 yv = *(const float4*)(smT + c * 132 + l4);
        float4 o4 = {xr.x + yv.x, xr.y + yv.y, xr.z + yv.z, xr.w + yv.w};
        *(float4*)(out + gi) = o4;
    }
}

// ---------------- beta = sigmoid(t @ Wb) ----------------
__global__ void __launch_bounds__(256) beta_kernel(const float* __restrict__ x, const float* __restrict__ Wb) {
    __shared__ float As[16 * 128];
    __shared__ float Wbs[16 * 12];
    const int tid = threadIdx.x;
    const int m0 = blockIdx.x * 128;
    const int b = m0 / LDIM, l0 = m0 % LDIM;
    const float* xb = x + (size_t)b * CDIM * LDIM + l0;
    const int row = tid & 127, hset = tid >> 7;
    float acc[6] = {0, 0, 0, 0, 0, 0};
    for (int k0 = 0; k0 < CDIM; k0 += 16) {
#pragma unroll
        for (int i = 0; i < 8; i++) {
            int idx = tid + i * 256;
            As[(idx >> 7) * 128 + (idx & 127)] = xb[(size_t)(k0 + (idx >> 7)) * LDIM + (idx & 127)];
        }
        if (tid < 192) Wbs[(tid / 12) * 12 + tid % 12] = Wb[(size_t)(k0 + tid / 12) * NH + tid % 12];
        __syncthreads();
#pragma unroll
        for (int kk = 0; kk < 16; kk++) {
            float a = As[kk * 128 + row];
#pragma unroll
            for (int j = 0; j < 6; j++) acc[j] = fmaf(a, Wbs[kk * 12 + hset * 6 + j], acc[j]);
        }
        __syncthreads();
    }
#pragma unroll
    for (int j = 0; j < 6; j++)
        g_beta[(size_t)(b * NH + hset * 6 + j) * LDIM + l0 + row] = 1.f / (1.f + __expf(-acc[j]));
}

// ---------------- chunkwise delta-rule scan ----------------
#define DELTA_SMEM_FLOATS (6 * 64 * SP + 64)
__global__ void __launch_bounds__(256) delta_kernel() {
    extern __shared__ float smd[];
    float* S  = smd;
    float* qs = smd + 1 * 64 * SP;
    float* ks = smd + 2 * 64 * SP;
    float* vs = smd + 3 * 64 * SP;
    float* us = smd + 4 * 64 * SP;
    float* A  = smd + 5 * 64 * SP;
    float* bvec = smd + 6 * 64 * SP;

    const int tid = threadIdx.x;
    const int bh = blockIdx.x;
    const int b = bh / NH, h = bh % NH;
    const float* qp = g_q + (size_t)bh * LDIM * HD;
    const float* kp = g_k + (size_t)bh * LDIM * HD;
    const float* vp = g_v + (size_t)bh * LDIM * HD;
    const float* bp = g_beta + (size_t)bh * LDIM;

    const int ty = tid >> 4, tx = tid & 15;
    const int i0 = ty * 4, j0 = tx * 4;

    for (int i = tid; i < 64 * SP; i += 256) S[i] = 0.f;
    __syncthreads();

    for (int ch = 0; ch < NCHK; ch++) {
        const int base = ch * CHK;
#pragma unroll
        for (int i = 0; i < 16; i++) {
            int idx = tid + i * 256;
            int r = idx >> 6, d = idx & 63;
            qs[r * SP + d] = qp[(size_t)(base + r) * HD + d];
            ks[r * SP + d] = kp[(size_t)(base + r) * HD + d];
            vs[r * SP + d] = vp[(size_t)(base + r) * HD + d];
        }
        if (tid < 64) bvec[tid] = bp[base + tid];
        __syncthreads();

        {   // A = strict_tril(beta_i * K K^T)
            float acc[4][4] = {};
            for (int d = 0; d < 64; d++) {
                float a[4], bb[4];
#pragma unroll
                for (int ii = 0; ii < 4; ii++) a[ii] = ks[(i0 + ii) * SP + d];
#pragma unroll
                for (int jj = 0; jj < 4; jj++) bb[jj] = ks[(j0 + jj) * SP + d];
#pragma unroll
                for (int ii = 0; ii < 4; ii++)
#pragma unroll
                    for (int jj = 0; jj < 4; jj++) acc[ii][jj] = fmaf(a[ii], bb[jj], acc[ii][jj]);
            }
#pragma unroll
            for (int ii = 0; ii < 4; ii++) {
                float bi = bvec[i0 + ii];
#pragma unroll
                for (int jj = 0; jj < 4; jj++)
                    A[(i0 + ii) * SP + j0 + jj] = (j0 + jj < i0 + ii) ? bi * acc[ii][jj] : 0.f;
            }
        }
        {   // us = beta_i * (V - K S)
            float acc[4][4] = {};
            for (int d = 0; d < 64; d++) {
                float a[4], s4[4];
#pragma unroll
                for (int ii = 0; ii < 4; ii++) a[ii] = ks[(i0 + ii) * SP + d];
#pragma unroll
                for (int jj = 0; jj < 4; jj++) s4[jj] = S[d * SP + j0 + jj];
#pragma unroll
                for (int ii = 0; ii < 4; ii++)
#pragma unroll
                    for (int jj = 0; jj < 4; jj++) acc[ii][jj] = fmaf(a[ii], s4[jj], acc[ii][jj]);
            }
#pragma unroll
            for (int ii = 0; ii < 4; ii++) {
                float bi = bvec[i0 + ii];
#pragma unroll
                for (int jj = 0; jj < 4; jj++)
                    us[(i0 + ii) * SP + j0 + jj] = bi * (vs[(i0 + ii) * SP + j0 + jj] - acc[ii][jj]);
            }
        }
        __syncthreads();

        for (int blk = 0; blk < 8; blk++) {   // forward substitution (I + A) U = us
            const int r0 = blk * 8;
            if (blk > 0) {
                int il = tid >> 5, e = (tid & 31) * 2;
                float a0 = 0.f, a1 = 0.f;
                for (int j = 0; j < r0; j++) {
                    float aij = A[(r0 + il) * SP + j];
                    a0 = fmaf(aij, us[j * SP + e], a0);
                    a1 = fmaf(aij, us[j * SP + e + 1], a1);
                }
                us[(r0 + il) * SP + e]     -= a0;
                us[(r0 + il) * SP + e + 1] -= a1;
            }
            __syncthreads();
            if (tid < 64) {
                const int e = tid;
                float u[8];
#pragma unroll
                for (int r = 0; r < 8; r++) u[r] = us[(r0 + r) * SP + e];
#pragma unroll
                for (int r = 1; r < 8; r++) {
                    float s = u[r];
#pragma unroll
                    for (int rr = 0; rr < r; rr++) s = fmaf(-A[(r0 + r) * SP + r0 + rr], u[rr], s);
                    u[r] = s;
                }
#pragma unroll
                for (int r = 1; r < 8; r++) us[(r0 + r) * SP + e] = u[r];
            }
            __syncthreads();
        }

        {   // A = incl_tril(Q K^T)
            float acc[4][4] = {};
            for (int d = 0; d < 64; d++) {
                float a[4], bb[4];
#pragma unroll
                for (int ii = 0; ii < 4; ii++) a[ii] = qs[(i0 + ii) * SP + d];
#pragma unroll
                for (int jj = 0; jj < 4; jj++) bb[jj] = ks[(j0 + jj) * SP + d];
#pragma unroll
                for (int ii = 0; ii < 4; ii++)
#pragma unroll
                    for (int jj = 0; jj < 4; jj++) acc[ii][jj] = fmaf(a[ii], bb[jj], acc[ii][jj]);
            }
#pragma unroll
            for (int ii = 0; ii < 4; ii++)
#pragma unroll
                for (int jj = 0; jj < 4; jj++)
                    A[(i0 + ii) * SP + j0 + jj] = (j0 + jj <= i0 + ii) ? acc[ii][jj] : 0.f;
        }
        __syncthreads();

        {   // O = Q S + A U -> vs
            float acc[4][4] = {};
            for (int d = 0; d < 64; d++) {
                float a[4], s4[4];
#pragma unroll
                for (int ii = 0; ii < 4; ii++) a[ii] = qs[(i0 + ii) * SP + d];
#pragma unroll
                for (int jj = 0; jj < 4; jj++) s4[jj] = S[d * SP + j0 + jj];
#pragma unroll
                for (int ii = 0; ii < 4; ii++)
#pragma unroll
                    for (int jj = 0; jj < 4; jj++) acc[ii][jj] = fmaf(a[ii], s4[jj], acc[ii][jj]);
            }
            for (int j = 0; j < 64; j++) {
                float a[4], u4[4];
#pragma unroll
                for (int ii = 0; ii < 4; ii++) a[ii] = A[(i0 + ii) * SP + j];
#pragma unroll
                for (int jj = 0; jj < 4; jj++) u4[jj] = us[j * SP + j0 + jj];
#pragma unroll
                for (int ii = 0; ii < 4; ii++)
#pragma unroll
                    for (int jj = 0; jj < 4; jj++) acc[ii][jj] = fmaf(a[ii], u4[jj], acc[ii][jj]);
            }
#pragma unroll
            for (int ii = 0; ii < 4; ii++)
#pragma unroll
                for (int jj = 0; jj < 4; jj++) vs[(i0 + ii) * SP + j0 + jj] = acc[ii][jj];
        }
        __syncthreads();

        // dump O as bf16 hi/lo to g_oh/g_ol ([m][c] layout)
#pragma unroll
        for (int i = 0; i < 16; i++) {
            int idx = tid + i * 256;
            int r = idx >> 6, e = idx & 63;
            float v = vs[r * SP + e];
            unsigned short hh, ll;
            hilo(v, hh, ll);
            size_t off = (size_t)(b * LDIM + base + r) * CDIM + h * HD + e;
            g_oh[off] = hh;
            g_ol[off] = ll;
        }
        {   // S += K^T U
            float acc[4][4] = {};
            for (int i = 0; i < 64; i++) {
                float a[4], u4[4];
#pragma unroll
                for (int dd = 0; dd < 4; dd++) a[dd] = ks[i * SP + i0 + dd];
#pragma unroll
                for (int ee = 0; ee < 4; ee++) u4[ee] = us[i * SP + j0 + ee];
#pragma unroll
                for (int dd = 0; dd < 4; dd++)
#pragma unroll
                    for (int ee = 0; ee < 4; ee++) acc[dd][ee] = fmaf(a[dd], u4[ee], acc[dd][ee]);
            }
#pragma unroll
            for (int dd = 0; dd < 4; dd++)
#pragma unroll
                for (int ee = 0; ee < 4; ee++) S[(i0 + dd) * SP + j0 + ee] += acc[dd][ee];
        }
        __syncthreads();
    }
}

// ---------------- launch ----------------
extern "C" void kernel_launch(void* const* d_in, const int* in_sizes, int n_in,
                              void* d_out, int out_size) {
    const float* x  = (const float*)d_in[0];
    const float* Wq = (const float*)d_in[1];
    const float* Wk = (const float*)d_in[2];
    const float* Wv = (const float*)d_in[3];
    const float* Wb = (const float*)d_in[4];
    const float* Wo = (const float*)d_in[5];
    float* out = (float*)d_out;

    cudaFuncSetAttribute(qkv_gemm, cudaFuncAttributeMaxDynamicSharedMemorySize, GEMM_SMEM);
    cudaFuncSetAttribute(out_gemm, cudaFuncAttributeMaxDynamicSharedMemorySize, GEMM_SMEM);
    cudaFuncSetAttribute(delta_kernel, cudaFuncAttributeMaxDynamicSharedMemorySize,
                         DELTA_SMEM_FLOATS * sizeof(float));

    prep_x<<<dim3(LDIM / 32, CDIM / 32, BSZ), 256>>>(x);
    prep_w<<<dim3(CDIM / 32, CDIM / 32, 4), 256>>>(Wq, Wk, Wv, Wo);
    beta_kernel<<<MTOT / 128, 256>>>(x, Wb);
    qkv_gemm<<<dim3(18, MTOT / 128), 256, GEMM_SMEM>>>();
    delta_kernel<<<BSZ * NH, 256, DELTA_SMEM_FLOATS * sizeof(float)>>>();
    out_gemm<<<dim3(6, MTOT / 128), 256, GEMM_SMEM>>>(x, out);
}

// round 11
// speedup vs baseline: 1.1586x; 1.1586x over previous
#include <cuda_runtime.h>
#include <cuda_bf16.h>
#include <cstdint>
#include <math.h>

#define BSZ 8
#define CDIM 768
#define LDIM 4096
#define NH 12
#define HD 64
#define CHK 64
#define NCHK (LDIM/CHK)
#define MTOT (BSZ*LDIM)

// ---------------- scratch (device globals; no allocation allowed) ----------------
__device__ unsigned short g_xh[(size_t)MTOT * CDIM];   // bf16 hi of x^T [m][k]
__device__ unsigned short g_xl[(size_t)MTOT * CDIM];   // bf16 lo
__device__ unsigned short g_wh[(size_t)4 * CDIM * CDIM]; // W^T [w*768+n][k], w: 0 q,1 k,2 v,3 o
__device__ unsigned short g_wl[(size_t)4 * CDIM * CDIM];
__device__ float g_q[(size_t)BSZ * NH * LDIM * HD];
__device__ float g_k[(size_t)BSZ * NH * LDIM * HD];
__device__ float g_v[(size_t)BSZ * NH * LDIM * HD];
__device__ float g_beta[(size_t)BSZ * NH * LDIM];
__device__ unsigned short g_oh[(size_t)MTOT * CDIM];   // bf16 hi of o [m][c]
__device__ unsigned short g_ol[(size_t)MTOT * CDIM];   // bf16 lo

// ---------------- PTX helpers (base-PTX only; no 'a' features) ----------------
__device__ __forceinline__ uint32_t smem_u32(const void* p) {
    return (uint32_t)__cvta_generic_to_shared(p);
}
__device__ __forceinline__ void cp16(uint32_t dst, const void* src) {
    asm volatile("cp.async.cg.shared.global [%0], [%1], 16;" :: "r"(dst), "l"(src) : "memory");
}
__device__ __forceinline__ void cp_commit() {
    asm volatile("cp.async.commit_group;" ::: "memory");
}
__device__ __forceinline__ void cp_wait2() {
    asm volatile("cp.async.wait_group 2;" ::: "memory");
}
__device__ __forceinline__ void cp_wait1() {
    asm volatile("cp.async.wait_group 1;" ::: "memory");
}
__device__ __forceinline__ void cp_wait0() {
    asm volatile("cp.async.wait_group 0;" ::: "memory");
}
__device__ __forceinline__ void ldsm_x4(uint32_t addr, uint32_t* r) {
    asm volatile("ldmatrix.sync.aligned.m8n8.x4.shared.b16 {%0,%1,%2,%3}, [%4];"
                 : "=r"(r[0]), "=r"(r[1]), "=r"(r[2]), "=r"(r[3]) : "r"(addr));
}
__device__ __forceinline__ void mma_bf16(float* d, const uint32_t* a, const uint32_t* b) {
    asm volatile("mma.sync.aligned.m16n8k16.row.col.f32.bf16.bf16.f32 "
                 "{%0,%1,%2,%3}, {%4,%5,%6,%7}, {%8,%9}, {%0,%1,%2,%3};"
                 : "+f"(d[0]), "+f"(d[1]), "+f"(d[2]), "+f"(d[3])
                 : "r"(a[0]), "r"(a[1]), "r"(a[2]), "r"(a[3]), "r"(b[0]), "r"(b[1]));
}
__device__ __forceinline__ void hilo(float v, unsigned short& h, unsigned short& l) {
    uint32_t u = __float_as_uint(v);
    h = (unsigned short)(u >> 16);
    float lf = v - __uint_as_float(u & 0xFFFF0000u);
    __nv_bfloat16 lb = __float2bfloat16(lf);
    l = *reinterpret_cast<unsigned short*>(&lb);
}

// ---------------- prep: transpose + hi/lo split ----------------
__global__ void __launch_bounds__(256) prep_x(const float* __restrict__ x) {
    __shared__ float t[32][33];
    const int tid = threadIdx.x;
    const int b = blockIdx.z, c0 = blockIdx.y * 32, l0 = blockIdx.x * 32;
    const int lt = tid & 31, ct = tid >> 5;
    const float* xb = x + ((size_t)b * CDIM + c0) * LDIM + l0;
#pragma unroll
    for (int i = 0; i < 4; i++) t[ct + 8 * i][lt] = xb[(size_t)(ct + 8 * i) * LDIM + lt];
    __syncthreads();
#pragma unroll
    for (int i = 0; i < 4; i++) {
        unsigned short h, l;
        hilo(t[lt][ct + 8 * i], h, l);
        size_t off = (size_t)(b * LDIM + l0 + ct + 8 * i) * CDIM + c0 + lt;
        g_xh[off] = h;
        g_xl[off] = l;
    }
}

__global__ void __launch_bounds__(256) prep_w(const float* __restrict__ Wq, const float* __restrict__ Wk,
                                              const float* __restrict__ Wv, const float* __restrict__ Wo) {
    __shared__ float t[32][33];
    const int tid = threadIdx.x;
    const int w = blockIdx.z, n0 = blockIdx.y * 32, k0 = blockIdx.x * 32;
    const int nt = tid & 31, kt = tid >> 5;
    const float* W = (w == 0) ? Wq : (w == 1) ? Wk : (w == 2) ? Wv : Wo;
#pragma unroll
    for (int i = 0; i < 4; i++) t[kt + 8 * i][nt] = W[(size_t)(k0 + kt + 8 * i) * CDIM + n0 + nt];
    __syncthreads();
#pragma unroll
    for (int i = 0; i < 4; i++) {
        unsigned short h, l;
        hilo(t[nt][kt + 8 * i], h, l);
        size_t off = (size_t)(w * CDIM + n0 + kt + 8 * i) * CDIM + k0 + nt;
        g_wh[off] = h;
        g_wl[off] = l;
    }
}

// ---------------- GEMM core: 128x128 block, 8 warps, K-chunk 32, 3 stages ----------------
// stage (32KB): Ah[128][32] @0, Al @8192, Bh @16384, Bl @24576 (bf16, 64B rows, SW64 swizzle)
#define STG 32768
#define NCH 24
#define GEMM_SMEM (3 * STG)

__device__ __forceinline__ void load_stage(uint32_t st,
                                           const unsigned short* Ah, const unsigned short* Al,
                                           const unsigned short* Bh, const unsigned short* Bl,
                                           int ch, int tid) {
#pragma unroll
    for (int i = 0; i < 8; i++) {
        int idx = tid + i * 256;
        int tile = idx >> 9, rem = idx & 511;
        int row = rem >> 2, j = rem & 3;
        const unsigned short* s0 = (tile == 0) ? Ah : (tile == 1) ? Al : (tile == 2) ? Bh : Bl;
        uint32_t off = row * 64 + j * 16;
        uint32_t sw = off ^ ((off >> 3) & 0x30);
        cp16(st + tile * 8192 + sw, s0 + (size_t)row * CDIM + ch * 32 + j * 8);
    }
}

__device__ __forceinline__ void gemm_compute(uint32_t st, float (&C)[2][8][4], int wid, int lane) {
    const int wm = wid >> 1, wn = wid & 1;
    const int rowA = wm * 32 + (lane & 15);
    const int byteA = (lane >> 4) * 16;
    const int rowB = wn * 64 + ((lane >> 4) & 1) * 8 + (lane & 7);
    const int byteB = ((lane >> 3) & 1) * 16;
#pragma unroll
    for (int kk = 0; kk < 2; kk++) {
        uint32_t ah[2][4], al[2][4];
#pragma unroll
        for (int ma = 0; ma < 2; ma++) {
            uint32_t off = (uint32_t)(rowA + ma * 16) * 64 + kk * 32 + byteA;
            uint32_t sw = off ^ ((off >> 3) & 0x30);
            ldsm_x4(st + sw, ah[ma]);
            ldsm_x4(st + 8192 + sw, al[ma]);
        }
#pragma unroll
        for (int jj = 0; jj < 4; jj++) {
            uint32_t bh[4], bl[4];
            uint32_t off = (uint32_t)(rowB + jj * 16) * 64 + kk * 32 + byteB;
            uint32_t sw = off ^ ((off >> 3) & 0x30);
            ldsm_x4(st + 16384 + sw, bh);
            ldsm_x4(st + 24576 + sw, bl);
#pragma unroll
            for (int ma = 0; ma < 2; ma++)
#pragma unroll
                for (int hh = 0; hh < 2; hh++) {
                    mma_bf16(C[ma][jj * 2 + hh], ah[ma], &bh[hh * 2]);
                    mma_bf16(C[ma][jj * 2 + hh], al[ma], &bh[hh * 2]);
                    mma_bf16(C[ma][jj * 2 + hh], ah[ma], &bl[hh * 2]);
                }
        }
    }
}

#define GEMM_PIPE(AH, AL, BH, BL)                                              \
    load_stage(sb, AH, AL, BH, BL, 0, tid); cp_commit();                       \
    load_stage(sb + STG, AH, AL, BH, BL, 1, tid); cp_commit();                 \
    for (int ch = 0; ch < NCH; ch++) {                                         \
        if (ch + 2 < NCH) {                                                    \
            int nb = (ch + 2) % 3;                                             \
            load_stage(sb + nb * STG, AH, AL, BH, BL, ch + 2, tid);            \
            cp_commit();                                                       \
            cp_wait2();                                                        \
        } else if (ch + 2 == NCH) { cp_wait1(); } else { cp_wait0(); }         \
        __syncthreads();                                                       \
        gemm_compute(sb + (ch % 3) * STG, C, wid, lane);                       \
        __syncthreads();                                                       \
    }

// ---------------- qkv GEMM: D = xt @ W^T, silu (+ l2norm for q,k) ----------------
__global__ void __launch_bounds__(256, 2) qkv_gemm() {
    extern __shared__ char smg[];
    const uint32_t sb = smem_u32(smg);
    const int tid = threadIdx.x, wid = tid >> 5, lane = tid & 31;
    const int nt = blockIdx.x;
    const int m0 = blockIdx.y * 128;
    const unsigned short* Ah = g_xh + (size_t)m0 * CDIM;
    const unsigned short* Al = g_xl + (size_t)m0 * CDIM;
    const unsigned short* Bh = g_wh + (size_t)(nt * 128) * CDIM;
    const unsigned short* Bl = g_wl + (size_t)(nt * 128) * CDIM;

    float C[2][8][4];
#pragma unroll
    for (int a = 0; a < 2; a++)
#pragma unroll
        for (int b = 0; b < 8; b++)
#pragma unroll
            for (int c = 0; c < 4; c++) C[a][b][c] = 0.f;

    GEMM_PIPE(Ah, Al, Bh, Bl)

    // epilogue
    const int wm = wid >> 1, wn = wid & 1;
    const int which = nt / 6;                 // 0 q, 1 k, 2 v
    const int head = (nt % 6) * 2 + wn;
    float* gout = (which == 0) ? g_q : (which == 1) ? g_k : g_v;
    const int g = lane >> 2, qd = lane & 3;
#pragma unroll
    for (int ma = 0; ma < 2; ma++) {
        float s[8][4];
        float ss0 = 0.f, ss1 = 0.f;
#pragma unroll
        for (int j = 0; j < 8; j++)
#pragma unroll
            for (int t = 0; t < 4; t++) {
                float v = C[ma][j][t];
                float sv = v / (1.f + __expf(-v));
                s[j][t] = sv;
                if (t < 2) ss0 = fmaf(sv, sv, ss0);
                else       ss1 = fmaf(sv, sv, ss1);
            }
        ss0 += __shfl_xor_sync(0xFFFFFFFFu, ss0, 1);
        ss0 += __shfl_xor_sync(0xFFFFFFFFu, ss0, 2);
        ss1 += __shfl_xor_sync(0xFFFFFFFFu, ss1, 1);
        ss1 += __shfl_xor_sync(0xFFFFFFFFu, ss1, 2);
        float sc0 = (which < 2) ? rsqrtf(ss0 + 1e-6f) : 1.f;
        float sc1 = (which < 2) ? rsqrtf(ss1 + 1e-6f) : 1.f;
#pragma unroll
        for (int half = 0; half < 2; half++) {
            int m = m0 + wm * 32 + ma * 16 + g + half * 8;
            int b = m >> 12, l = m & 4095;
            float sc = half ? sc1 : sc0;
            float* op = gout + ((size_t)(b * NH + head) * LDIM + l) * HD + qd * 2;
#pragma unroll
            for (int j = 0; j < 8; j++) {
                float2 o2 = {s[j][half * 2] * sc, s[j][half * 2 + 1] * sc};
                *(float2*)(op + j * 8) = o2;
            }
        }
    }
}

// ---------------- out GEMM: y = o @ Wo^T, out[b,c,l] = x + y^T ----------------
__global__ void __launch_bounds__(256, 2) out_gemm(const float* __restrict__ x, float* __restrict__ out) {
    extern __shared__ char smg2[];
    const uint32_t sb = smem_u32(smg2);
    const int tid = threadIdx.x, wid = tid >> 5, lane = tid & 31;
    const int n0 = blockIdx.x * 128;
    const int m0 = blockIdx.y * 128;
    const unsigned short* Ah = g_oh + (size_t)m0 * CDIM;
    const unsigned short* Al = g_ol + (size_t)m0 * CDIM;
    const unsigned short* Bh = g_wh + (size_t)(3 * CDIM + n0) * CDIM;
    const unsigned short* Bl = g_wl + (size_t)(3 * CDIM + n0) * CDIM;

    float C[2][8][4];
#pragma unroll
    for (int a = 0; a < 2; a++)
#pragma unroll
        for (int b = 0; b < 8; b++)
#pragma unroll
            for (int c = 0; c < 4; c++) C[a][b][c] = 0.f;

    GEMM_PIPE(Ah, Al, Bh, Bl)

    // epilogue: transpose through smem, residual add, coalesced [B,C,L] writes
    float* smT = (float*)smg2;   // [128 c][132]
    const int wm = wid >> 1, wn = wid & 1;
    const int g = lane >> 2, qd = lane & 3;
#pragma unroll
    for (int ma = 0; ma < 2; ma++)
#pragma unroll
        for (int j = 0; j < 8; j++) {
            int r = wm * 32 + ma * 16 + g;
            int c = wn * 64 + j * 8 + qd * 2;
            smT[c * 132 + r]           = C[ma][j][0];
            smT[(c + 1) * 132 + r]     = C[ma][j][1];
            smT[c * 132 + r + 8]       = C[ma][j][2];
            smT[(c + 1) * 132 + r + 8] = C[ma][j][3];
        }
    __syncthreads();

    const int b = m0 >> 12, l0 = m0 & 4095;
#pragma unroll
    for (int i = 0; i < 16; i++) {
        int u = tid + i * 256;
        int c = u >> 5, l4 = (u & 31) * 4;
        size_t gi = ((size_t)b * CDIM + n0 + c) * LDIM + l0 + l4;
        float4 xr = *(const float4*)(x + gi);
        float4 yv = *(const float4*)(smT + c * 132 + l4);
        float4 o4 = {xr.x + yv.x, xr.y + yv.y, xr.z + yv.z, xr.w + yv.w};
        *(float4*)(out + gi) = o4;
    }
}

// ---------------- beta = sigmoid(t @ Wb) ----------------
__global__ void __launch_bounds__(256) beta_kernel(const float* __restrict__ x, const float* __restrict__ Wb) {
    __shared__ float As[16 * 128];
    __shared__ float Wbs[16 * 12];
    const int tid = threadIdx.x;
    const int m0 = blockIdx.x * 128;
    const int b = m0 / LDIM, l0 = m0 % LDIM;
    const float* xb = x + (size_t)b * CDIM * LDIM + l0;
    const int row = tid & 127, hset = tid >> 7;
    float acc[6] = {0, 0, 0, 0, 0, 0};
    for (int k0 = 0; k0 < CDIM; k0 += 16) {
#pragma unroll
        for (int i = 0; i < 8; i++) {
            int idx = tid + i * 256;
            As[(idx >> 7) * 128 + (idx & 127)] = xb[(size_t)(k0 + (idx >> 7)) * LDIM + (idx & 127)];
        }
        if (tid < 192) Wbs[(tid / 12) * 12 + tid % 12] = Wb[(size_t)(k0 + tid / 12) * NH + tid % 12];
        __syncthreads();
#pragma unroll
        for (int kk = 0; kk < 16; kk++) {
            float a = As[kk * 128 + row];
#pragma unroll
            for (int j = 0; j < 6; j++) acc[j] = fmaf(a, Wbs[kk * 12 + hset * 6 + j], acc[j]);
        }
        __syncthreads();
    }
#pragma unroll
    for (int j = 0; j < 6; j++)
        g_beta[(size_t)(b * NH + hset * 6 + j) * LDIM + l0 + row] = 1.f / (1.f + __expf(-acc[j]));
}

// ---------------- chunkwise delta-rule scan: fused float4 version ----------------
#define DSP 68
#define DELTA_SMEM_FLOATS (8 * 64 * DSP + 64)
__global__ void __launch_bounds__(256) delta_kernel() {
    extern __shared__ float smd[];
    float* S   = smd;                 // S[d][e] fp32 master
    float* ksT = smd + 1 * 64 * DSP;  // ksT[d][i] = k[i][d]
    float* qsT = smd + 2 * 64 * DSP;  // qsT[d][i] = q[i][d]
    float* ks  = smd + 3 * 64 * DSP;  // k[i][d]
    float* vs  = smd + 4 * 64 * DSP;  // v[i][e]
    float* us  = smd + 5 * 64 * DSP;  // u[i][e]
    float* A   = smd + 6 * 64 * DSP;  // strict tril(beta KK^T), row-major (solve)
    float* AT  = smd + 7 * 64 * DSP;  // incl tril(Q K^T) transposed: AT[j][i]
    float* bvec = smd + 8 * 64 * DSP;

    const int tid = threadIdx.x;
    const int bh = blockIdx.x;
    const int b = bh / NH, h = bh % NH;
    const float* qp = g_q + (size_t)bh * LDIM * HD;
    const float* kp = g_k + (size_t)bh * LDIM * HD;
    const float* vp = g_v + (size_t)bh * LDIM * HD;
    const float* bp = g_beta + (size_t)bh * LDIM;

    const int ty = tid >> 4, tx = tid & 15;
    const int i0 = ty * 4, j0 = tx * 4;

    for (int i = tid; i < 64 * DSP; i += 256) S[i] = 0.f;
    __syncthreads();

    for (int ch = 0; ch < NCHK; ch++) {
        const int base = ch * CHK;
        // ---- load q,k,v chunk (float4 global), build transposed copies
#pragma unroll
        for (int i = 0; i < 4; i++) {
            int idx = tid + i * 256;
            int r = idx >> 4, d4 = (idx & 15) * 4;
            float4 q4 = *(const float4*)(qp + (size_t)(base + r) * HD + d4);
            float4 k4 = *(const float4*)(kp + (size_t)(base + r) * HD + d4);
            float4 v4 = *(const float4*)(vp + (size_t)(base + r) * HD + d4);
            qsT[(d4 + 0) * DSP + r] = q4.x; qsT[(d4 + 1) * DSP + r] = q4.y;
            qsT[(d4 + 2) * DSP + r] = q4.z; qsT[(d4 + 3) * DSP + r] = q4.w;
            ksT[(d4 + 0) * DSP + r] = k4.x; ksT[(d4 + 1) * DSP + r] = k4.y;
            ksT[(d4 + 2) * DSP + r] = k4.z; ksT[(d4 + 3) * DSP + r] = k4.w;
            *(float4*)(ks + r * DSP + d4) = k4;
            *(float4*)(vs + r * DSP + d4) = v4;
        }
        if (tid < 64) bvec[tid] = bp[base + tid];
        __syncthreads();

        // ---- phase1 (fused): akk = K K^T tile, aks = (K S) tile
        float akk[4][4] = {}, aks[4][4] = {};
#pragma unroll 4
        for (int d = 0; d < 64; d++) {
            float4 a4 = *(const float4*)(ksT + d * DSP + i0);
            float4 b4 = *(const float4*)(ksT + d * DSP + j0);
            float4 s4 = *(const float4*)(S + d * DSP + j0);
            float av[4] = {a4.x, a4.y, a4.z, a4.w};
            float bv[4] = {b4.x, b4.y, b4.z, b4.w};
            float sv[4] = {s4.x, s4.y, s4.z, s4.w};
#pragma unroll
            for (int ii = 0; ii < 4; ii++)
#pragma unroll
                for (int jj = 0; jj < 4; jj++) {
                    akk[ii][jj] = fmaf(av[ii], bv[jj], akk[ii][jj]);
                    aks[ii][jj] = fmaf(av[ii], sv[jj], aks[ii][jj]);
                }
        }
#pragma unroll
        for (int ii = 0; ii < 4; ii++) {
            float bi = bvec[i0 + ii];
            float4 v4 = *(const float4*)(vs + (i0 + ii) * DSP + j0);
            float4 ar, ur;
            ar.x = (j0 + 0 < i0 + ii) ? bi * akk[ii][0] : 0.f;
            ar.y = (j0 + 1 < i0 + ii) ? bi * akk[ii][1] : 0.f;
            ar.z = (j0 + 2 < i0 + ii) ? bi * akk[ii][2] : 0.f;
            ar.w = (j0 + 3 < i0 + ii) ? bi * akk[ii][3] : 0.f;
            ur.x = bi * (v4.x - aks[ii][0]);
            ur.y = bi * (v4.y - aks[ii][1]);
            ur.z = bi * (v4.z - aks[ii][2]);
            ur.w = bi * (v4.w - aks[ii][3]);
            *(float4*)(A + (i0 + ii) * DSP + j0) = ar;
            *(float4*)(us + (i0 + ii) * DSP + j0) = ur;
        }
        __syncthreads();

        // ---- forward substitution (I + A) U = us, blocked 8 rows
        for (int blk = 0; blk < 8; blk++) {
            const int r0 = blk * 8;
            if (blk > 0 && tid < 128) {
                int il = tid >> 4, q4 = (tid & 15) * 4;
                float a0 = 0.f, a1 = 0.f, a2 = 0.f, a3 = 0.f;
                for (int j = 0; j < r0; j++) {
                    float a = A[(r0 + il) * DSP + j];
                    float4 u4 = *(const float4*)(us + j * DSP + q4);
                    a0 = fmaf(a, u4.x, a0);
                    a1 = fmaf(a, u4.y, a1);
                    a2 = fmaf(a, u4.z, a2);
                    a3 = fmaf(a, u4.w, a3);
                }
                float4 cur = *(const float4*)(us + (r0 + il) * DSP + q4);
                cur.x -= a0; cur.y -= a1; cur.z -= a2; cur.w -= a3;
                *(float4*)(us + (r0 + il) * DSP + q4) = cur;
            }
            __syncthreads();
            if (tid < 64) {
                const int e = tid;
                float u[8];
#pragma unroll
                for (int r = 0; r < 8; r++) u[r] = us[(r0 + r) * DSP + e];
#pragma unroll
                for (int r = 1; r < 8; r++) {
                    float s = u[r];
#pragma unroll
                    for (int rr = 0; rr < r; rr++) s = fmaf(-A[(r0 + r) * DSP + r0 + rr], u[rr], s);
                    u[r] = s;
                }
#pragma unroll
                for (int r = 1; r < 8; r++) us[(r0 + r) * DSP + e] = u[r];
            }
            __syncthreads();
        }

        // ---- phase3 (fused): aqk = Q K^T tile (-> AT masked), aqs = (Q S) tile (kept in regs)
        float aqk[4][4] = {}, aqs[4][4] = {};
#pragma unroll 4
        for (int d = 0; d < 64; d++) {
            float4 a4 = *(const float4*)(qsT + d * DSP + i0);
            float4 b4 = *(const float4*)(ksT + d * DSP + j0);
            float4 s4 = *(const float4*)(S + d * DSP + j0);
            float av[4] = {a4.x, a4.y, a4.z, a4.w};
            float bv[4] = {b4.x, b4.y, b4.z, b4.w};
            float sv[4] = {s4.x, s4.y, s4.z, s4.w};
#pragma unroll
            for (int ii = 0; ii < 4; ii++)
#pragma unroll
                for (int jj = 0; jj < 4; jj++) {
                    aqk[ii][jj] = fmaf(av[ii], bv[jj], aqk[ii][jj]);
                    aqs[ii][jj] = fmaf(av[ii], sv[jj], aqs[ii][jj]);
                }
        }
#pragma unroll
        for (int ii = 0; ii < 4; ii++)
#pragma unroll
            for (int jj = 0; jj < 4; jj++)
                AT[(j0 + jj) * DSP + (i0 + ii)] = (j0 + jj <= i0 + ii) ? aqk[ii][jj] : 0.f;
        __syncthreads();

        // ---- phase5 (fused): ao = (tril(QK^T) U) tile, asu = (K^T U) tile
        float ao[4][4] = {}, asu[4][4] = {};
#pragma unroll 4
        for (int i = 0; i < 64; i++) {
            float4 aA = *(const float4*)(AT + i * DSP + i0);
            float4 aK = *(const float4*)(ks + i * DSP + i0);
            float4 u4 = *(const float4*)(us + i * DSP + j0);
            float av[4] = {aA.x, aA.y, aA.z, aA.w};
            float kv[4] = {aK.x, aK.y, aK.z, aK.w};
            float uv[4] = {u4.x, u4.y, u4.z, u4.w};
#pragma unroll
            for (int ii = 0; ii < 4; ii++)
#pragma unroll
                for (int jj = 0; jj < 4; jj++) {
                    ao[ii][jj]  = fmaf(av[ii], uv[jj], ao[ii][jj]);
                    asu[ii][jj] = fmaf(kv[ii], uv[jj], asu[ii][jj]);
                }
        }
        // S += K^T U (thread-exclusive tiles)
#pragma unroll
        for (int ii = 0; ii < 4; ii++) {
            float4 sc = *(const float4*)(S + (i0 + ii) * DSP + j0);
            sc.x += asu[ii][0]; sc.y += asu[ii][1];
            sc.z += asu[ii][2]; sc.w += asu[ii][3];
            *(float4*)(S + (i0 + ii) * DSP + j0) = sc;
        }
        // O = Q S + tril(QK^T) U  -> hi/lo bf16, direct global write (8B per row per thread)
        unsigned short* ohp = g_oh + (size_t)(b * LDIM + base) * CDIM + h * HD;
        unsigned short* olp = g_ol + (size_t)(b * LDIM + base) * CDIM + h * HD;
#pragma unroll
        for (int ii = 0; ii < 4; ii++) {
            unsigned short hi[4], lo[4];
#pragma unroll
            for (int jj = 0; jj < 4; jj++) {
                float o = aqs[ii][jj] + ao[ii][jj];
                hilo(o, hi[jj], lo[jj]);
            }
            uint2 hv = {(uint32_t)hi[0] | ((uint32_t)hi[1] << 16),
                        (uint32_t)hi[2] | ((uint32_t)hi[3] << 16)};
            uint2 lv = {(uint32_t)lo[0] | ((uint32_t)lo[1] << 16),
                        (uint32_t)lo[2] | ((uint32_t)lo[3] << 16)};
            size_t off = (size_t)(i0 + ii) * CDIM + j0;
            *(uint2*)(ohp + off) = hv;
            *(uint2*)(olp + off) = lv;
        }
        __syncthreads();
    }
}

// ---------------- launch ----------------
extern "C" void kernel_launch(void* const* d_in, const int* in_sizes, int n_in,
                              void* d_out, int out_size) {
    const float* x  = (const float*)d_in[0];
    const float* Wq = (const float*)d_in[1];
    const float* Wk = (const float*)d_in[2];
    const float* Wv = (const float*)d_in[3];
    const float* Wb = (const float*)d_in[4];
    const float* Wo = (const float*)d_in[5];
    float* out = (float*)d_out;

    cudaFuncSetAttribute(qkv_gemm, cudaFuncAttributeMaxDynamicSharedMemorySize, GEMM_SMEM);
    cudaFuncSetAttribute(out_gemm, cudaFuncAttributeMaxDynamicSharedMemorySize, GEMM_SMEM);
    cudaFuncSetAttribute(delta_kernel, cudaFuncAttributeMaxDynamicSharedMemorySize,
                         DELTA_SMEM_FLOATS * sizeof(float));

    prep_x<<<dim3(LDIM / 32, CDIM / 32, BSZ), 256>>>(x);
    prep_w<<<dim3(CDIM / 32, CDIM / 32, 4), 256>>>(Wq, Wk, Wv, Wo);
    beta_kernel<<<MTOT / 128, 256>>>(x, Wb);
    qkv_gemm<<<dim3(18, MTOT / 128), 256, GEMM_SMEM>>>();
    delta_kernel<<<BSZ * NH, 256, DELTA_SMEM_FLOATS * sizeof(float)>>>();
    out_gemm<<<dim3(6, MTOT / 128), 256, GEMM_SMEM>>>(x, out);
}